// round 1
// baseline (speedup 1.0000x reference)
#include <cuda_runtime.h>
#include <math_constants.h>
#include <cstdint>

// Problem constants
#define BATCH 2
#define SEQ   2048
#define MODEL 1024
#define HEADS 16
#define HDIM  64
#define ROWS  (BATCH*SEQ)          // 4096
#define QKVN  (3*MODEL)            // 3072

// Scratch (device globals: allocation-free)
__device__ float g_qkv[(size_t)ROWS * QKVN];   // [4096][3072]
__device__ float g_z  [(size_t)ROWS * MODEL];  // [4096][1024]

// ---------------------------------------------------------------------------
// SGEMM: C[M,N] = A[M,K] @ B[K,N] + bias[N]
// 128x128 tile, BK=16, 256 threads, 8x8 per thread.
// ---------------------------------------------------------------------------
#define GBM 128
#define GBN 128
#define GBK 16

__global__ __launch_bounds__(256) void sgemm128(
    const float* __restrict__ A, const float* __restrict__ Bm,
    const float* __restrict__ bias, float* __restrict__ C,
    int Md, int Nd, int Kd)
{
    __shared__ float As[GBK][GBM + 4];   // transposed A tile, padded
    __shared__ float Bs[GBK][GBN];

    const int tid = threadIdx.x;
    const int bn = blockIdx.x * GBN;
    const int bm = blockIdx.y * GBM;
    const int tx = tid & 15;
    const int ty = tid >> 4;

    // global load mapping
    const int arow = tid >> 2;            // 0..63
    const int acol = (tid & 3) * 4;       // 0,4,8,12
    const int brow = tid >> 5;            // 0..7
    const int bcol = (tid & 31) * 4;      // 0..124

    const float* Aptr = A + (size_t)(bm + arow) * Kd + acol;
    const float* Bptr = Bm + (size_t)brow * Nd + bn + bcol;

    float acc[8][8];
#pragma unroll
    for (int i = 0; i < 8; i++)
#pragma unroll
        for (int j = 0; j < 8; j++) acc[i][j] = 0.f;

    for (int k0 = 0; k0 < Kd; k0 += GBK) {
        float4 a0 = *(const float4*)(Aptr + k0);
        float4 a1 = *(const float4*)(Aptr + (size_t)64 * Kd + k0);
        float4 b0 = *(const float4*)(Bptr + (size_t)k0 * Nd);
        float4 b1 = *(const float4*)(Bptr + (size_t)(k0 + 8) * Nd);

        As[acol + 0][arow] = a0.x; As[acol + 1][arow] = a0.y;
        As[acol + 2][arow] = a0.z; As[acol + 3][arow] = a0.w;
        As[acol + 0][arow + 64] = a1.x; As[acol + 1][arow + 64] = a1.y;
        As[acol + 2][arow + 64] = a1.z; As[acol + 3][arow + 64] = a1.w;
        *(float4*)&Bs[brow][bcol]     = b0;
        *(float4*)&Bs[brow + 8][bcol] = b1;
        __syncthreads();

#pragma unroll
        for (int kk = 0; kk < GBK; kk++) {
            float4 af0 = *(const float4*)&As[kk][ty * 8];
            float4 af1 = *(const float4*)&As[kk][ty * 8 + 4];
            float4 bf0 = *(const float4*)&Bs[kk][tx * 8];
            float4 bf1 = *(const float4*)&Bs[kk][tx * 8 + 4];
            float av[8] = {af0.x, af0.y, af0.z, af0.w, af1.x, af1.y, af1.z, af1.w};
            float bv[8] = {bf0.x, bf0.y, bf0.z, bf0.w, bf1.x, bf1.y, bf1.z, bf1.w};
#pragma unroll
            for (int i = 0; i < 8; i++)
#pragma unroll
                for (int j = 0; j < 8; j++)
                    acc[i][j] += av[i] * bv[j];
        }
        __syncthreads();
    }

    // epilogue with bias, float4 stores
    const int cn = bn + tx * 8;
    float4 bb0 = *(const float4*)(bias + cn);
    float4 bb1 = *(const float4*)(bias + cn + 4);
#pragma unroll
    for (int i = 0; i < 8; i++) {
        size_t row = (size_t)(bm + ty * 8 + i);
        float4 o0 = make_float4(acc[i][0] + bb0.x, acc[i][1] + bb0.y,
                                acc[i][2] + bb0.z, acc[i][3] + bb0.w);
        float4 o1 = make_float4(acc[i][4] + bb1.x, acc[i][5] + bb1.y,
                                acc[i][6] + bb1.z, acc[i][7] + bb1.w);
        *(float4*)(C + row * Nd + cn)     = o0;
        *(float4*)(C + row * Nd + cn + 4) = o1;
    }
}

// ---------------------------------------------------------------------------
// Flash-style causal attention.
// One CTA per (q-tile of 64 rows, head, batch). KV tiles of 64.
// 256 threads, each owning a 4x4 patch of the 64x64 score / output tiles.
// Transposed smem tiles so inner loops are float4 outer-products.
// ---------------------------------------------------------------------------
#define PAD 68
#define ASMEM (4 * 64 * PAD * (int)sizeof(float))   // Qt,Kt,Vs,Pt = 69632 B

__global__ __launch_bounds__(256) void attn_kernel(
    const float* __restrict__ qkv, float* __restrict__ z)
{
    extern __shared__ float sm[];
    float* Qt = sm;                  // [d][r]  64x68
    float* Kt = sm + 64 * PAD;       // [d][c]
    float* Vs = sm + 2 * 64 * PAD;   // [c][dv]
    float* Pt = sm + 3 * 64 * PAD;   // [c][r]

    const int tid = threadIdx.x;
    const int qb = blockIdx.x;   // 0..31
    const int h  = blockIdx.y;   // 0..15
    const int bb = blockIdx.z;   // 0..1

    const int pr = tid >> 4;          // 0..15
    const int pc = tid & 15;          // 0..15
    const int r0 = pr * 4;
    const int c0 = pc * 4;

    const size_t rs = QKVN;
    const float* qbase = qkv + ((size_t)bb * SEQ + qb * 64) * rs + h * HDIM;

#pragma unroll
    for (int i = 0; i < 16; i++) {
        int idx = i * 256 + tid;
        int r = idx >> 6, d = idx & 63;
        Qt[d * PAD + r] = qbase[(size_t)r * rs + d] * 0.125f;
    }
    __syncthreads();

    float m[4], l[4], o[16];
#pragma unroll
    for (int i = 0; i < 4; i++) { m[i] = -CUDART_INF_F; l[i] = 0.f; }
#pragma unroll
    for (int i = 0; i < 16; i++) o[i] = 0.f;

    for (int kb = 0; kb <= qb; kb++) {
        const float* kbase = qkv + ((size_t)bb * SEQ + kb * 64) * rs + MODEL + h * HDIM;
        const float* vbase = kbase + MODEL;
#pragma unroll
        for (int i = 0; i < 16; i++) {
            int idx = i * 256 + tid;
            int r = idx >> 6, d = idx & 63;
            Kt[d * PAD + r] = kbase[(size_t)r * rs + d];
            Vs[r * PAD + d] = vbase[(size_t)r * rs + d];
        }
        __syncthreads();

        // S = Q K^T  (4x4 patch per thread)
        float s[16];
#pragma unroll
        for (int t = 0; t < 16; t++) s[t] = 0.f;
#pragma unroll 8
        for (int d = 0; d < 64; d++) {
            float4 q4 = *(const float4*)(Qt + d * PAD + r0);
            float4 k4 = *(const float4*)(Kt + d * PAD + c0);
            float qv[4] = {q4.x, q4.y, q4.z, q4.w};
            float kv[4] = {k4.x, k4.y, k4.z, k4.w};
#pragma unroll
            for (int i = 0; i < 4; i++)
#pragma unroll
                for (int j = 0; j < 4; j++)
                    s[i * 4 + j] += qv[i] * kv[j];
        }

        if (kb == qb) {
#pragma unroll
            for (int i = 0; i < 4; i++)
#pragma unroll
                for (int j = 0; j < 4; j++)
                    if (c0 + j > r0 + i) s[i * 4 + j] = -CUDART_INF_F;
        }

        // online softmax per row (row group = 16 consecutive lanes)
#pragma unroll
        for (int i = 0; i < 4; i++) {
            float mx = fmaxf(fmaxf(s[i*4], s[i*4+1]), fmaxf(s[i*4+2], s[i*4+3]));
            mx = fmaxf(mx, __shfl_xor_sync(0xffffffffu, mx, 1));
            mx = fmaxf(mx, __shfl_xor_sync(0xffffffffu, mx, 2));
            mx = fmaxf(mx, __shfl_xor_sync(0xffffffffu, mx, 4));
            mx = fmaxf(mx, __shfl_xor_sync(0xffffffffu, mx, 8));
            float mn = fmaxf(m[i], mx);
            float corr = __expf(m[i] - mn);
            float rsum = 0.f;
#pragma unroll
            for (int j = 0; j < 4; j++) {
                float pv = __expf(s[i*4+j] - mn);
                s[i*4+j] = pv;
                rsum += pv;
            }
            rsum += __shfl_xor_sync(0xffffffffu, rsum, 1);
            rsum += __shfl_xor_sync(0xffffffffu, rsum, 2);
            rsum += __shfl_xor_sync(0xffffffffu, rsum, 4);
            rsum += __shfl_xor_sync(0xffffffffu, rsum, 8);
            l[i] = l[i] * corr + rsum;
            m[i] = mn;
            o[i*4+0] *= corr; o[i*4+1] *= corr; o[i*4+2] *= corr; o[i*4+3] *= corr;
            Pt[(c0+0) * PAD + r0 + i] = s[i*4+0];
            Pt[(c0+1) * PAD + r0 + i] = s[i*4+1];
            Pt[(c0+2) * PAD + r0 + i] = s[i*4+2];
            Pt[(c0+3) * PAD + r0 + i] = s[i*4+3];
        }
        __syncthreads();

        // O += P V
#pragma unroll 8
        for (int c = 0; c < 64; c++) {
            float4 p4 = *(const float4*)(Pt + c * PAD + r0);
            float4 v4 = *(const float4*)(Vs + c * PAD + c0);
            float pv[4] = {p4.x, p4.y, p4.z, p4.w};
            float vv[4] = {v4.x, v4.y, v4.z, v4.w};
#pragma unroll
            for (int i = 0; i < 4; i++)
#pragma unroll
                for (int j = 0; j < 4; j++)
                    o[i * 4 + j] += pv[i] * vv[j];
        }
        __syncthreads();
    }

    float* zbase = z + ((size_t)bb * SEQ + qb * 64) * MODEL + h * HDIM;
#pragma unroll
    for (int i = 0; i < 4; i++) {
        float inv = 1.f / l[i];
        float4 ov = make_float4(o[i*4+0]*inv, o[i*4+1]*inv, o[i*4+2]*inv, o[i*4+3]*inv);
        *(float4*)(zbase + (size_t)(r0 + i) * MODEL + c0) = ov;
    }
}

// ---------------------------------------------------------------------------
// Launch
// ---------------------------------------------------------------------------
extern "C" void kernel_launch(void* const* d_in, const int* in_sizes, int n_in,
                              void* d_out, int out_size)
{
    const float* x      = (const float*)d_in[0];
    const float* W_attn = (const float*)d_in[1];
    const float* b_attn = (const float*)d_in[2];
    const float* W_proj = (const float*)d_in[3];
    const float* b_proj = (const float*)d_in[4];
    float* out = (float*)d_out;

    float *qkv, *z;
    cudaGetSymbolAddress((void**)&qkv, g_qkv);
    cudaGetSymbolAddress((void**)&z,   g_z);

    cudaFuncSetAttribute(attn_kernel,
                         cudaFuncAttributeMaxDynamicSharedMemorySize, ASMEM);

    // QKV projection: [4096,1024] @ [1024,3072]
    sgemm128<<<dim3(QKVN / GBN, ROWS / GBM), 256>>>(
        x, W_attn, b_attn, qkv, ROWS, QKVN, MODEL);

    // causal attention -> z [4096,1024]
    attn_kernel<<<dim3(SEQ / 64, HEADS, BATCH), 256, ASMEM>>>(qkv, z);

    // output projection: [4096,1024] @ [1024,1024]
    sgemm128<<<dim3(MODEL / GBN, ROWS / GBM), 256>>>(
        z, W_proj, b_proj, out, ROWS, MODEL, MODEL);
}

// round 4
// speedup vs baseline: 1.4713x; 1.4713x over previous
#include <cuda_runtime.h>
#include <cuda_bf16.h>
#include <math_constants.h>
#include <cstdint>

// Problem constants
#define BATCH 2
#define SEQ   2048
#define MODEL 1024
#define HEADS 16
#define HDIM  64
#define ROWS  (BATCH*SEQ)          // 4096
#define QKVN  (3*MODEL)            // 3072
#define KDIM  1024

// ---------------------------------------------------------------------------
// Scratch (device globals: allocation-free)
// ---------------------------------------------------------------------------
__device__ float         g_qkv[(size_t)ROWS * QKVN];
__device__ __nv_bfloat16 g_xh[(size_t)ROWS * KDIM];
__device__ __nv_bfloat16 g_xl[(size_t)ROWS * KDIM];
__device__ __nv_bfloat16 g_wah[(size_t)QKVN * KDIM];
__device__ __nv_bfloat16 g_wal[(size_t)QKVN * KDIM];
__device__ __nv_bfloat16 g_wph[(size_t)MODEL * KDIM];
__device__ __nv_bfloat16 g_wpl[(size_t)MODEL * KDIM];
__device__ __nv_bfloat16 g_zh[(size_t)ROWS * MODEL];
__device__ __nv_bfloat16 g_zl[(size_t)ROWS * MODEL];

// ---------------------------------------------------------------------------
// Helpers
// ---------------------------------------------------------------------------
__device__ __forceinline__ uint32_t smem_u32(const void* p) {
    uint32_t a;
    asm("{ .reg .u64 t; cvta.to.shared.u64 t, %1; cvt.u32.u64 %0, t; }"
        : "=r"(a) : "l"(p));
    return a;
}
__device__ __forceinline__ void ldm_x4(uint32_t* r, uint32_t a) {
    asm volatile("ldmatrix.sync.aligned.m8n8.x4.shared.b16 {%0,%1,%2,%3}, [%4];"
        : "=r"(r[0]), "=r"(r[1]), "=r"(r[2]), "=r"(r[3]) : "r"(a));
}
__device__ __forceinline__ void mma16816(float* c, const uint32_t* a, const uint32_t* b) {
    asm volatile("mma.sync.aligned.m16n8k16.row.col.f32.bf16.bf16.f32 "
        "{%0,%1,%2,%3}, {%4,%5,%6,%7}, {%8,%9}, {%0,%1,%2,%3};"
        : "+f"(c[0]), "+f"(c[1]), "+f"(c[2]), "+f"(c[3])
        : "r"(a[0]), "r"(a[1]), "r"(a[2]), "r"(a[3]), "r"(b[0]), "r"(b[1]));
}
__device__ __forceinline__ void cp16(uint32_t saddr, const void* gaddr) {
    asm volatile("cp.async.cg.shared.global [%0], [%1], 16;" :: "r"(saddr), "l"(gaddr));
}

// ---------------------------------------------------------------------------
// Prep: fp32 -> bf16 hi/lo split (element-wise, same layout)
// ---------------------------------------------------------------------------
__global__ void split_convert(const float* __restrict__ x,
                              __nv_bfloat16* __restrict__ h,
                              __nv_bfloat16* __restrict__ l, int n4)
{
    int i = blockIdx.x * blockDim.x + threadIdx.x;
    if (i >= n4) return;
    float4 v = ((const float4*)x)[i];
    __nv_bfloat16 h0 = __float2bfloat16(v.x), h1 = __float2bfloat16(v.y);
    __nv_bfloat16 h2 = __float2bfloat16(v.z), h3 = __float2bfloat16(v.w);
    __nv_bfloat16 l0 = __float2bfloat16(v.x - __bfloat162float(h0));
    __nv_bfloat16 l1 = __float2bfloat16(v.y - __bfloat162float(h1));
    __nv_bfloat16 l2 = __float2bfloat16(v.z - __bfloat162float(h2));
    __nv_bfloat16 l3 = __float2bfloat16(v.w - __bfloat162float(h3));
    __nv_bfloat162 ph0 = __halves2bfloat162(h0, h1), ph1 = __halves2bfloat162(h2, h3);
    __nv_bfloat162 pl0 = __halves2bfloat162(l0, l1), pl1 = __halves2bfloat162(l2, l3);
    uint2 uh, ul;
    uh.x = *reinterpret_cast<uint32_t*>(&ph0); uh.y = *reinterpret_cast<uint32_t*>(&ph1);
    ul.x = *reinterpret_cast<uint32_t*>(&pl0); ul.y = *reinterpret_cast<uint32_t*>(&pl1);
    ((uint2*)h)[i] = uh;
    ((uint2*)l)[i] = ul;
}

// ---------------------------------------------------------------------------
// Prep: W[K][N] fp32 -> W^T hi/lo bf16 [N][K]
// ---------------------------------------------------------------------------
__global__ void transpose_split(const float* __restrict__ W,
                                __nv_bfloat16* __restrict__ Th,
                                __nv_bfloat16* __restrict__ Tl,
                                int Kd, int Nd)
{
    __shared__ float t[32][33];
    int n0 = blockIdx.x * 32, k0 = blockIdx.y * 32;
    int tx = threadIdx.x, ty = threadIdx.y;
#pragma unroll
    for (int j = 0; j < 32; j += 8)
        t[ty + j][tx] = W[(size_t)(k0 + ty + j) * Nd + n0 + tx];
    __syncthreads();
#pragma unroll
    for (int j = 0; j < 32; j += 8) {
        float v = t[tx][ty + j];
        int n = n0 + ty + j, k = k0 + tx;
        __nv_bfloat16 hb = __float2bfloat16(v);
        __nv_bfloat16 lb = __float2bfloat16(v - __bfloat162float(hb));
        Th[(size_t)n * Kd + k] = hb;
        Tl[(size_t)n * Kd + k] = lb;
    }
}

// ---------------------------------------------------------------------------
// mma.sync split-bf16 GEMM: C[M,Nd] = A[M,1024] @ W[1024,Nd] + bias
//   A hi/lo bf16 [row][k]; W hi/lo bf16 transposed [n][k].
// CTA 128x128, BK=64, 8 warps (4 M x 2 N), warp tile 32x64.
// cp.async double-buffered smem, ldmatrix fragments, 3-pass accumulation.
// ---------------------------------------------------------------------------
#define GPITCH 144
#define GTILEB (128 * GPITCH)                 // 18432 B
#define GSTAGEB (4 * GTILEB)                  // 73728 B
#define GSMEM  (2 * GSTAGEB)                  // 147456 B

__global__ __launch_bounds__(256, 1) void gemm_mma(
    const __nv_bfloat16* __restrict__ Ah, const __nv_bfloat16* __restrict__ Al,
    const __nv_bfloat16* __restrict__ Bh, const __nv_bfloat16* __restrict__ Bl,
    const float* __restrict__ bias, float* __restrict__ C, int Nd)
{
    extern __shared__ char smem[];
    const uint32_t sbase = smem_u32(smem);
    const int tid  = threadIdx.x;
    const int wid  = tid >> 5, lane = tid & 31;
    const int bn   = blockIdx.x * 128;
    const int bm   = blockIdx.y * 128;
    const int wm0  = (wid & 3) * 32;
    const int wn0  = (wid >> 2) * 64;

    // global->smem loader mapping: 16B chunk per thread
    const int lrow = tid >> 3;          // 0..31
    const int lc   = tid & 7;           // 0..7 (16B chunks across 64 bf16)

    const __nv_bfloat16* srcA_h = Ah + (size_t)bm * KDIM;
    const __nv_bfloat16* srcA_l = Al + (size_t)bm * KDIM;
    const __nv_bfloat16* srcB_h = Bh + (size_t)bn * KDIM;
    const __nv_bfloat16* srcB_l = Bl + (size_t)bn * KDIM;

    // ldmatrix lane addressing
    const int arow  = (lane & 7) + ((lane >> 3) & 1) * 8;   // row within m16
    const int acolB = ((lane >> 4) & 1) * 16;               // 0 or 16 bytes
    const int brow  = (lane & 7) + ((lane >> 4) & 1) * 8;   // row within n16
    const int bcolB = ((lane >> 3) & 1) * 16;

    float acc[16][4];
#pragma unroll
    for (int i = 0; i < 16; i++)
#pragma unroll
        for (int j = 0; j < 4; j++) acc[i][j] = 0.f;

    // stage issue
    auto issue = [&](int stage, int k0) {
        uint32_t so = sbase + stage * GSTAGEB + lrow * GPITCH + lc * 16;
        const __nv_bfloat16* gA_h = srcA_h + (size_t)lrow * KDIM + k0 + lc * 8;
        const __nv_bfloat16* gA_l = srcA_l + (size_t)lrow * KDIM + k0 + lc * 8;
        const __nv_bfloat16* gB_h = srcB_h + (size_t)lrow * KDIM + k0 + lc * 8;
        const __nv_bfloat16* gB_l = srcB_l + (size_t)lrow * KDIM + k0 + lc * 8;
#pragma unroll
        for (int i = 0; i < 4; i++) {
            uint32_t sa = so + i * 32 * GPITCH;
            size_t   go = (size_t)i * 32 * KDIM;
            cp16(sa,               gA_h + go);
            cp16(sa + GTILEB,      gA_l + go);
            cp16(sa + 2 * GTILEB,  gB_h + go);
            cp16(sa + 3 * GTILEB,  gB_l + go);
        }
        asm volatile("cp.async.commit_group;" ::: "memory");
    };

    issue(0, 0);

    for (int c = 0; c < 16; c++) {
        if (c + 1 < 16) {
            issue((c + 1) & 1, (c + 1) * 64);
            asm volatile("cp.async.wait_group 1;" ::: "memory");
        } else {
            asm volatile("cp.async.wait_group 0;" ::: "memory");
        }
        __syncthreads();

        const uint32_t ab  = sbase + (c & 1) * GSTAGEB;
        const uint32_t alb = ab + GTILEB;
        const uint32_t bb  = ab + 2 * GTILEB;
        const uint32_t blb = ab + 3 * GTILEB;

#pragma unroll
        for (int ks = 0; ks < 4; ks++) {
            uint32_t fah[2][4], fal[2][4], fbh[4][4], fbl[4][4];
#pragma unroll
            for (int ma = 0; ma < 2; ma++) {
                uint32_t off = (uint32_t)(wm0 + ma * 16 + arow) * GPITCH + ks * 32 + acolB;
                ldm_x4(fah[ma], ab + off);
                ldm_x4(fal[ma], alb + off);
            }
#pragma unroll
            for (int na = 0; na < 4; na++) {
                uint32_t off = (uint32_t)(wn0 + na * 16 + brow) * GPITCH + ks * 32 + bcolB;
                ldm_x4(fbh[na], bb + off);
                ldm_x4(fbl[na], blb + off);
            }
#pragma unroll
            for (int ma = 0; ma < 2; ma++) {
#pragma unroll
                for (int na = 0; na < 4; na++) {
                    float* c0 = acc[ma * 8 + na * 2];
                    float* c1 = acc[ma * 8 + na * 2 + 1];
                    mma16816(c0, fah[ma], fbh[na]);       // hi*hi
                    mma16816(c1, fah[ma], fbh[na] + 2);
                    mma16816(c0, fah[ma], fbl[na]);       // hi*lo
                    mma16816(c1, fah[ma], fbl[na] + 2);
                    mma16816(c0, fal[ma], fbh[na]);       // lo*hi
                    mma16816(c1, fal[ma], fbh[na] + 2);
                }
            }
        }
        __syncthreads();
    }

    // epilogue: bias + direct stores
    const int er = bm + wm0 + (lane >> 2);
    const int ec = bn + wn0 + (lane & 3) * 2;
#pragma unroll
    for (int ma = 0; ma < 2; ma++) {
#pragma unroll
        for (int na = 0; na < 8; na++) {
            const float* a4 = acc[ma * 8 + na];
            int row = er + ma * 16;
            int col = ec + na * 8;
            float b0 = __ldg(bias + col), b1 = __ldg(bias + col + 1);
            float2 v0 = make_float2(a4[0] + b0, a4[1] + b1);
            float2 v1 = make_float2(a4[2] + b0, a4[3] + b1);
            *(float2*)(C + (size_t)row * Nd + col)       = v0;
            *(float2*)(C + (size_t)(row + 8) * Nd + col) = v1;
        }
    }
}

// ---------------------------------------------------------------------------
// Flash-style causal attention (fp32), outputs z as bf16 hi/lo.
// ---------------------------------------------------------------------------
#define PAD 68
#define ASMEM (4 * 64 * PAD * (int)sizeof(float))

__global__ __launch_bounds__(256) void attn_kernel(
    const float* __restrict__ qkv,
    __nv_bfloat16* __restrict__ zh, __nv_bfloat16* __restrict__ zl)
{
    extern __shared__ float sm[];
    float* Qt = sm;
    float* Kt = sm + 64 * PAD;
    float* Vs = sm + 2 * 64 * PAD;
    float* Pt = sm + 3 * 64 * PAD;

    const int tid = threadIdx.x;
    const int qb = blockIdx.x;
    const int h  = blockIdx.y;
    const int bb = blockIdx.z;

    const int pr = tid >> 4;
    const int pc = tid & 15;
    const int r0 = pr * 4;
    const int c0 = pc * 4;

    const size_t rs = QKVN;
    const float* qbase = qkv + ((size_t)bb * SEQ + qb * 64) * rs + h * HDIM;

#pragma unroll
    for (int i = 0; i < 16; i++) {
        int idx = i * 256 + tid;
        int r = idx >> 6, d = idx & 63;
        Qt[d * PAD + r] = qbase[(size_t)r * rs + d] * 0.125f;
    }
    __syncthreads();

    float m[4], l[4], o[16];
#pragma unroll
    for (int i = 0; i < 4; i++) { m[i] = -CUDART_INF_F; l[i] = 0.f; }
#pragma unroll
    for (int i = 0; i < 16; i++) o[i] = 0.f;

    for (int kb = 0; kb <= qb; kb++) {
        const float* kbase = qkv + ((size_t)bb * SEQ + kb * 64) * rs + MODEL + h * HDIM;
        const float* vbase = kbase + MODEL;
#pragma unroll
        for (int i = 0; i < 16; i++) {
            int idx = i * 256 + tid;
            int r = idx >> 6, d = idx & 63;
            Kt[d * PAD + r] = kbase[(size_t)r * rs + d];
            Vs[r * PAD + d] = vbase[(size_t)r * rs + d];
        }
        __syncthreads();

        float s[16];
#pragma unroll
        for (int t = 0; t < 16; t++) s[t] = 0.f;
#pragma unroll 8
        for (int d = 0; d < 64; d++) {
            float4 q4 = *(const float4*)(Qt + d * PAD + r0);
            float4 k4 = *(const float4*)(Kt + d * PAD + c0);
            float qv[4] = {q4.x, q4.y, q4.z, q4.w};
            float kv[4] = {k4.x, k4.y, k4.z, k4.w};
#pragma unroll
            for (int i = 0; i < 4; i++)
#pragma unroll
                for (int j = 0; j < 4; j++)
                    s[i * 4 + j] += qv[i] * kv[j];
        }

        if (kb == qb) {
#pragma unroll
            for (int i = 0; i < 4; i++)
#pragma unroll
                for (int j = 0; j < 4; j++)
                    if (c0 + j > r0 + i) s[i * 4 + j] = -CUDART_INF_F;
        }

#pragma unroll
        for (int i = 0; i < 4; i++) {
            float mx = fmaxf(fmaxf(s[i*4], s[i*4+1]), fmaxf(s[i*4+2], s[i*4+3]));
            mx = fmaxf(mx, __shfl_xor_sync(0xffffffffu, mx, 1));
            mx = fmaxf(mx, __shfl_xor_sync(0xffffffffu, mx, 2));
            mx = fmaxf(mx, __shfl_xor_sync(0xffffffffu, mx, 4));
            mx = fmaxf(mx, __shfl_xor_sync(0xffffffffu, mx, 8));
            float mn = fmaxf(m[i], mx);
            float corr = __expf(m[i] - mn);
            float rsum = 0.f;
#pragma unroll
            for (int j = 0; j < 4; j++) {
                float pv = __expf(s[i*4+j] - mn);
                s[i*4+j] = pv;
                rsum += pv;
            }
            rsum += __shfl_xor_sync(0xffffffffu, rsum, 1);
            rsum += __shfl_xor_sync(0xffffffffu, rsum, 2);
            rsum += __shfl_xor_sync(0xffffffffu, rsum, 4);
            rsum += __shfl_xor_sync(0xffffffffu, rsum, 8);
            l[i] = l[i] * corr + rsum;
            m[i] = mn;
            o[i*4+0] *= corr; o[i*4+1] *= corr; o[i*4+2] *= corr; o[i*4+3] *= corr;
            Pt[(c0+0) * PAD + r0 + i] = s[i*4+0];
            Pt[(c0+1) * PAD + r0 + i] = s[i*4+1];
            Pt[(c0+2) * PAD + r0 + i] = s[i*4+2];
            Pt[(c0+3) * PAD + r0 + i] = s[i*4+3];
        }
        __syncthreads();

#pragma unroll 8
        for (int c = 0; c < 64; c++) {
            float4 p4 = *(const float4*)(Pt + c * PAD + r0);
            float4 v4 = *(const float4*)(Vs + c * PAD + c0);
            float pv[4] = {p4.x, p4.y, p4.z, p4.w};
            float vv[4] = {v4.x, v4.y, v4.z, v4.w};
#pragma unroll
            for (int i = 0; i < 4; i++)
#pragma unroll
                for (int j = 0; j < 4; j++)
                    o[i * 4 + j] += pv[i] * vv[j];
        }
        __syncthreads();
    }

    const size_t zoff = ((size_t)bb * SEQ + qb * 64) * MODEL + h * HDIM;
#pragma unroll
    for (int i = 0; i < 4; i++) {
        float inv = 1.f / l[i];
        float v0 = o[i*4+0]*inv, v1 = o[i*4+1]*inv, v2 = o[i*4+2]*inv, v3 = o[i*4+3]*inv;
        __nv_bfloat16 h0 = __float2bfloat16(v0), h1 = __float2bfloat16(v1);
        __nv_bfloat16 h2 = __float2bfloat16(v2), h3 = __float2bfloat16(v3);
        __nv_bfloat16 l0 = __float2bfloat16(v0 - __bfloat162float(h0));
        __nv_bfloat16 l1 = __float2bfloat16(v1 - __bfloat162float(h1));
        __nv_bfloat16 l2 = __float2bfloat16(v2 - __bfloat162float(h2));
        __nv_bfloat16 l3 = __float2bfloat16(v3 - __bfloat162float(h3));
        __nv_bfloat162 phh0 = __halves2bfloat162(h0, h1), phh1 = __halves2bfloat162(h2, h3);
        __nv_bfloat162 pll0 = __halves2bfloat162(l0, l1), pll1 = __halves2bfloat162(l2, l3);
        uint2 uh, ul;
        uh.x = *reinterpret_cast<uint32_t*>(&phh0); uh.y = *reinterpret_cast<uint32_t*>(&phh1);
        ul.x = *reinterpret_cast<uint32_t*>(&pll0); ul.y = *reinterpret_cast<uint32_t*>(&pll1);
        *(uint2*)(zh + zoff + (size_t)(r0 + i) * MODEL + c0) = uh;
        *(uint2*)(zl + zoff + (size_t)(r0 + i) * MODEL + c0) = ul;
    }
}

// ---------------------------------------------------------------------------
// Launch
// ---------------------------------------------------------------------------
extern "C" void kernel_launch(void* const* d_in, const int* in_sizes, int n_in,
                              void* d_out, int out_size)
{
    const float* x      = (const float*)d_in[0];
    const float* W_attn = (const float*)d_in[1];
    const float* b_attn = (const float*)d_in[2];
    const float* W_proj = (const float*)d_in[3];
    const float* b_proj = (const float*)d_in[4];
    float* out = (float*)d_out;

    float* qkv;             cudaGetSymbolAddress((void**)&qkv, g_qkv);
    __nv_bfloat16 *xh, *xl, *wah, *wal, *wph, *wpl, *zh, *zl;
    cudaGetSymbolAddress((void**)&xh,  g_xh);
    cudaGetSymbolAddress((void**)&xl,  g_xl);
    cudaGetSymbolAddress((void**)&wah, g_wah);
    cudaGetSymbolAddress((void**)&wal, g_wal);
    cudaGetSymbolAddress((void**)&wph, g_wph);
    cudaGetSymbolAddress((void**)&wpl, g_wpl);
    cudaGetSymbolAddress((void**)&zh,  g_zh);
    cudaGetSymbolAddress((void**)&zl,  g_zl);

    cudaFuncSetAttribute(gemm_mma, cudaFuncAttributeMaxDynamicSharedMemorySize, GSMEM);
    cudaFuncSetAttribute(attn_kernel, cudaFuncAttributeMaxDynamicSharedMemorySize, ASMEM);

    // Prep: split x; transpose+split weights
    split_convert<<<(ROWS * KDIM / 4 + 255) / 256, 256>>>(x, xh, xl, ROWS * KDIM / 4);
    transpose_split<<<dim3(QKVN / 32, KDIM / 32), dim3(32, 8)>>>(W_attn, wah, wal, KDIM, QKVN);
    transpose_split<<<dim3(MODEL / 32, KDIM / 32), dim3(32, 8)>>>(W_proj, wph, wpl, KDIM, MODEL);

    // QKV projection (tensor cores, 3-pass split bf16)
    gemm_mma<<<dim3(QKVN / 128, ROWS / 128), 256, GSMEM>>>(
        xh, xl, wah, wal, b_attn, qkv, QKVN);

    // causal attention -> z (bf16 hi/lo)
    attn_kernel<<<dim3(SEQ / 64, HEADS, BATCH), 256, ASMEM>>>(qkv, zh, zl);

    // output projection (tensor cores)
    gemm_mma<<<dim3(MODEL / 128, ROWS / 128), 256, GSMEM>>>(
        zh, zl, wph, wpl, b_proj, out, MODEL);
}

// round 6
// speedup vs baseline: 2.2192x; 1.5084x over previous
#include <cuda_runtime.h>
#include <cuda_bf16.h>
#include <math_constants.h>
#include <cstdint>

// Problem constants
#define BATCH 2
#define SEQ   2048
#define MODEL 1024
#define HEADS 16
#define HDIM  64
#define ROWS  (BATCH*SEQ)          // 4096
#define QKVN  (3*MODEL)            // 3072
#define KDIM  1024

// ---------------------------------------------------------------------------
// Scratch (device globals: allocation-free)
// ---------------------------------------------------------------------------
__device__ float         g_qkv[(size_t)ROWS * QKVN];
__device__ __nv_bfloat16 g_xh[(size_t)ROWS * KDIM];
__device__ __nv_bfloat16 g_xl[(size_t)ROWS * KDIM];
__device__ __nv_bfloat16 g_wah[(size_t)QKVN * KDIM];
__device__ __nv_bfloat16 g_wal[(size_t)QKVN * KDIM];
__device__ __nv_bfloat16 g_wph[(size_t)MODEL * KDIM];
__device__ __nv_bfloat16 g_wpl[(size_t)MODEL * KDIM];
__device__ __nv_bfloat16 g_zh[(size_t)ROWS * MODEL];
__device__ __nv_bfloat16 g_zl[(size_t)ROWS * MODEL];

// ---------------------------------------------------------------------------
// Helpers
// ---------------------------------------------------------------------------
__device__ __forceinline__ uint32_t smem_u32(const void* p) {
    uint32_t a;
    asm("{ .reg .u64 t; cvta.to.shared.u64 t, %1; cvt.u32.u64 %0, t; }"
        : "=r"(a) : "l"(p));
    return a;
}
__device__ __forceinline__ void ldm_x4(uint32_t* r, uint32_t a) {
    asm volatile("ldmatrix.sync.aligned.m8n8.x4.shared.b16 {%0,%1,%2,%3}, [%4];"
        : "=r"(r[0]), "=r"(r[1]), "=r"(r[2]), "=r"(r[3]) : "r"(a));
}
__device__ __forceinline__ void ldm_x4_t(uint32_t* r, uint32_t a) {
    asm volatile("ldmatrix.sync.aligned.m8n8.x4.trans.shared.b16 {%0,%1,%2,%3}, [%4];"
        : "=r"(r[0]), "=r"(r[1]), "=r"(r[2]), "=r"(r[3]) : "r"(a));
}
__device__ __forceinline__ void mma16816(float* c, const uint32_t* a, const uint32_t* b) {
    asm volatile("mma.sync.aligned.m16n8k16.row.col.f32.bf16.bf16.f32 "
        "{%0,%1,%2,%3}, {%4,%5,%6,%7}, {%8,%9}, {%0,%1,%2,%3};"
        : "+f"(c[0]), "+f"(c[1]), "+f"(c[2]), "+f"(c[3])
        : "r"(a[0]), "r"(a[1]), "r"(a[2]), "r"(a[3]), "r"(b[0]), "r"(b[1]));
}
__device__ __forceinline__ void cp16(uint32_t saddr, const void* gaddr) {
    asm volatile("cp.async.cg.shared.global [%0], [%1], 16;" :: "r"(saddr), "l"(gaddr));
}
// pack two floats as bf16x2: low half = a, high half = b
__device__ __forceinline__ uint32_t packbf(float a, float b) {
    uint32_t r;
    asm("cvt.rn.satfinite.bf16x2.f32 %0, %1, %2;" : "=r"(r) : "f"(b), "f"(a));
    return r;
}
__device__ __forceinline__ void split4(float4 v, uint2& h, uint2& l) {
    __nv_bfloat16 h0 = __float2bfloat16(v.x), h1 = __float2bfloat16(v.y);
    __nv_bfloat16 h2 = __float2bfloat16(v.z), h3 = __float2bfloat16(v.w);
    __nv_bfloat16 l0 = __float2bfloat16(v.x - __bfloat162float(h0));
    __nv_bfloat16 l1 = __float2bfloat16(v.y - __bfloat162float(h1));
    __nv_bfloat16 l2 = __float2bfloat16(v.z - __bfloat162float(h2));
    __nv_bfloat16 l3 = __float2bfloat16(v.w - __bfloat162float(h3));
    __nv_bfloat162 ph0 = __halves2bfloat162(h0, h1), ph1 = __halves2bfloat162(h2, h3);
    __nv_bfloat162 pl0 = __halves2bfloat162(l0, l1), pl1 = __halves2bfloat162(l2, l3);
    h.x = *reinterpret_cast<uint32_t*>(&ph0); h.y = *reinterpret_cast<uint32_t*>(&ph1);
    l.x = *reinterpret_cast<uint32_t*>(&pl0); l.y = *reinterpret_cast<uint32_t*>(&pl1);
}

// ---------------------------------------------------------------------------
// Prep: fp32 -> bf16 hi/lo split (element-wise, same layout)
// ---------------------------------------------------------------------------
__global__ void split_convert(const float* __restrict__ x,
                              __nv_bfloat16* __restrict__ h,
                              __nv_bfloat16* __restrict__ l, int n4)
{
    int i = blockIdx.x * blockDim.x + threadIdx.x;
    if (i >= n4) return;
    float4 v = ((const float4*)x)[i];
    uint2 uh, ul;
    split4(v, uh, ul);
    ((uint2*)h)[i] = uh;
    ((uint2*)l)[i] = ul;
}

// ---------------------------------------------------------------------------
// Prep: W[K][N] fp32 -> W^T hi/lo bf16 [N][K]
// ---------------------------------------------------------------------------
__global__ void transpose_split(const float* __restrict__ W,
                                __nv_bfloat16* __restrict__ Th,
                                __nv_bfloat16* __restrict__ Tl,
                                int Kd, int Nd)
{
    __shared__ float t[32][33];
    int n0 = blockIdx.x * 32, k0 = blockIdx.y * 32;
    int tx = threadIdx.x, ty = threadIdx.y;
#pragma unroll
    for (int j = 0; j < 32; j += 8)
        t[ty + j][tx] = W[(size_t)(k0 + ty + j) * Nd + n0 + tx];
    __syncthreads();
#pragma unroll
    for (int j = 0; j < 32; j += 8) {
        float v = t[tx][ty + j];
        int n = n0 + ty + j, k = k0 + tx;
        __nv_bfloat16 hb = __float2bfloat16(v);
        __nv_bfloat16 lb = __float2bfloat16(v - __bfloat162float(hb));
        Th[(size_t)n * Kd + k] = hb;
        Tl[(size_t)n * Kd + k] = lb;
    }
}

// ---------------------------------------------------------------------------
// mma.sync split-bf16 GEMM (unchanged from R4 passing version)
// ---------------------------------------------------------------------------
#define GPITCH 144
#define GTILEB (128 * GPITCH)
#define GSTAGEB (4 * GTILEB)
#define GSMEM  (2 * GSTAGEB)

__global__ __launch_bounds__(256, 1) void gemm_mma(
    const __nv_bfloat16* __restrict__ Ah, const __nv_bfloat16* __restrict__ Al,
    const __nv_bfloat16* __restrict__ Bh, const __nv_bfloat16* __restrict__ Bl,
    const float* __restrict__ bias, float* __restrict__ C, int Nd)
{
    extern __shared__ char smem[];
    const uint32_t sbase = smem_u32(smem);
    const int tid  = threadIdx.x;
    const int wid  = tid >> 5, lane = tid & 31;
    const int bn   = blockIdx.x * 128;
    const int bm   = blockIdx.y * 128;
    const int wm0  = (wid & 3) * 32;
    const int wn0  = (wid >> 2) * 64;

    const int lrow = tid >> 3;
    const int lc   = tid & 7;

    const __nv_bfloat16* srcA_h = Ah + (size_t)bm * KDIM;
    const __nv_bfloat16* srcA_l = Al + (size_t)bm * KDIM;
    const __nv_bfloat16* srcB_h = Bh + (size_t)bn * KDIM;
    const __nv_bfloat16* srcB_l = Bl + (size_t)bn * KDIM;

    const int arow  = (lane & 7) + ((lane >> 3) & 1) * 8;
    const int acolB = ((lane >> 4) & 1) * 16;
    const int brow  = (lane & 7) + ((lane >> 4) & 1) * 8;
    const int bcolB = ((lane >> 3) & 1) * 16;

    float acc[16][4];
#pragma unroll
    for (int i = 0; i < 16; i++)
#pragma unroll
        for (int j = 0; j < 4; j++) acc[i][j] = 0.f;

    auto issue = [&](int stage, int k0) {
        uint32_t so = sbase + stage * GSTAGEB + lrow * GPITCH + lc * 16;
        const __nv_bfloat16* gA_h = srcA_h + (size_t)lrow * KDIM + k0 + lc * 8;
        const __nv_bfloat16* gA_l = srcA_l + (size_t)lrow * KDIM + k0 + lc * 8;
        const __nv_bfloat16* gB_h = srcB_h + (size_t)lrow * KDIM + k0 + lc * 8;
        const __nv_bfloat16* gB_l = srcB_l + (size_t)lrow * KDIM + k0 + lc * 8;
#pragma unroll
        for (int i = 0; i < 4; i++) {
            uint32_t sa = so + i * 32 * GPITCH;
            size_t   go = (size_t)i * 32 * KDIM;
            cp16(sa,               gA_h + go);
            cp16(sa + GTILEB,      gA_l + go);
            cp16(sa + 2 * GTILEB,  gB_h + go);
            cp16(sa + 3 * GTILEB,  gB_l + go);
        }
        asm volatile("cp.async.commit_group;" ::: "memory");
    };

    issue(0, 0);

    for (int c = 0; c < 16; c++) {
        if (c + 1 < 16) {
            issue((c + 1) & 1, (c + 1) * 64);
            asm volatile("cp.async.wait_group 1;" ::: "memory");
        } else {
            asm volatile("cp.async.wait_group 0;" ::: "memory");
        }
        __syncthreads();

        const uint32_t ab  = sbase + (c & 1) * GSTAGEB;
        const uint32_t alb = ab + GTILEB;
        const uint32_t bb  = ab + 2 * GTILEB;
        const uint32_t blb = ab + 3 * GTILEB;

#pragma unroll
        for (int ks = 0; ks < 4; ks++) {
            uint32_t fah[2][4], fal[2][4], fbh[4][4], fbl[4][4];
#pragma unroll
            for (int ma = 0; ma < 2; ma++) {
                uint32_t off = (uint32_t)(wm0 + ma * 16 + arow) * GPITCH + ks * 32 + acolB;
                ldm_x4(fah[ma], ab + off);
                ldm_x4(fal[ma], alb + off);
            }
#pragma unroll
            for (int na = 0; na < 4; na++) {
                uint32_t off = (uint32_t)(wn0 + na * 16 + brow) * GPITCH + ks * 32 + bcolB;
                ldm_x4(fbh[na], bb + off);
                ldm_x4(fbl[na], blb + off);
            }
#pragma unroll
            for (int ma = 0; ma < 2; ma++) {
#pragma unroll
                for (int na = 0; na < 4; na++) {
                    float* c0 = acc[ma * 8 + na * 2];
                    float* c1 = acc[ma * 8 + na * 2 + 1];
                    mma16816(c0, fah[ma], fbh[na]);
                    mma16816(c1, fah[ma], fbh[na] + 2);
                    mma16816(c0, fah[ma], fbl[na]);
                    mma16816(c1, fah[ma], fbl[na] + 2);
                    mma16816(c0, fal[ma], fbh[na]);
                    mma16816(c1, fal[ma], fbh[na] + 2);
                }
            }
        }
        __syncthreads();
    }

    const int er = bm + wm0 + (lane >> 2);
    const int ec = bn + wn0 + (lane & 3) * 2;
#pragma unroll
    for (int ma = 0; ma < 2; ma++) {
#pragma unroll
        for (int na = 0; na < 8; na++) {
            const float* a4 = acc[ma * 8 + na];
            int row = er + ma * 16;
            int col = ec + na * 8;
            float b0 = __ldg(bias + col), b1 = __ldg(bias + col + 1);
            float2 v0 = make_float2(a4[0] + b0, a4[1] + b1);
            float2 v1 = make_float2(a4[2] + b0, a4[3] + b1);
            *(float2*)(C + (size_t)row * Nd + col)       = v0;
            *(float2*)(C + (size_t)(row + 8) * Nd + col) = v1;
        }
    }
}

// ---------------------------------------------------------------------------
// Tensor-core causal flash attention (split bf16, 3-pass), outputs z hi/lo.
// CTA: 64 q-rows x (head, batch); 4 warps, each warp m16 x 64.
// ---------------------------------------------------------------------------
#define APITCH 72                          // bf16 elems per row (144 B)
// smem regions (byte offsets): Qh,Ql,Kh,Kl,Vh,Vl each 64*144 = 9216 B
#define AQH 0
#define AQL 9216
#define AKH 18432
#define AKL 27648
#define AVH 36864
#define AVL 46080
#define ASMEMB 55296

__global__ __launch_bounds__(128) void attn_mma(
    const float* __restrict__ qkv,
    __nv_bfloat16* __restrict__ zh, __nv_bfloat16* __restrict__ zl)
{
    extern __shared__ __nv_bfloat16 asmem[];
    const uint32_t sb = smem_u32(asmem);
    const int tid = threadIdx.x, lane = tid & 31, wid = tid >> 5;
    const int qb = blockIdx.x, h = blockIdx.y, bb = blockIdx.z;

    // ---- load Q tile (64x64), scale by 1/8, split hi/lo ----
    {
        const int row = tid >> 1, ch = (tid & 1) * 32;
        const float* qg = qkv + ((size_t)(bb * SEQ + qb * 64 + row)) * QKVN + h * HDIM + ch;
#pragma unroll
        for (int j = 0; j < 8; j++) {
            float4 v = *(const float4*)(qg + j * 4);
            v.x *= 0.125f; v.y *= 0.125f; v.z *= 0.125f; v.w *= 0.125f;
            uint2 uh, ul;
            split4(v, uh, ul);
            int eo = row * APITCH + ch + j * 4;
            *(uint2*)((char*)asmem + AQH + eo * 2) = uh;
            *(uint2*)((char*)asmem + AQL + eo * 2) = ul;
        }
    }
    __syncthreads();

    // ---- Q fragments (held in registers for whole kernel) ----
    const int arow  = (lane & 7) + ((lane >> 3) & 1) * 8;
    const int acolB = ((lane >> 4) & 1) * 16;
    uint32_t qfh[4][4], qfl[4][4];
#pragma unroll
    for (int ks = 0; ks < 4; ks++) {
        uint32_t off = (uint32_t)(wid * 16 + arow) * (APITCH * 2) + ks * 32 + acolB;
        ldm_x4(qfh[ks], sb + AQH + off);
        ldm_x4(qfl[ks], sb + AQL + off);
    }

    float m0 = -CUDART_INF_F, m1 = -CUDART_INF_F, l0 = 0.f, l1 = 0.f;
    float o[8][4];
#pragma unroll
    for (int i = 0; i < 8; i++)
#pragma unroll
        for (int j = 0; j < 4; j++) o[i][j] = 0.f;

    const int brow  = (lane & 7) + ((lane >> 4) & 1) * 8;
    const int bcolB = ((lane >> 3) & 1) * 16;
    const int vrow  = (lane & 7) + ((lane >> 3) & 1) * 8;
    const int vcol8 = ((lane >> 4) & 1) * 8;

    for (int kb = 0; kb <= qb; kb++) {
        __syncthreads();   // previous tile's smem reads done
        // ---- load K,V tiles (64x64 each), split hi/lo ----
        {
            const int row = tid >> 1, ch = (tid & 1) * 32;
            const float* kg = qkv + ((size_t)(bb * SEQ + kb * 64 + row)) * QKVN
                              + MODEL + h * HDIM + ch;
            const float* vg = kg + MODEL;
#pragma unroll
            for (int j = 0; j < 8; j++) {
                int eo = row * APITCH + ch + j * 4;
                uint2 uh, ul;
                split4(*(const float4*)(kg + j * 4), uh, ul);
                *(uint2*)((char*)asmem + AKH + eo * 2) = uh;
                *(uint2*)((char*)asmem + AKL + eo * 2) = ul;
                split4(*(const float4*)(vg + j * 4), uh, ul);
                *(uint2*)((char*)asmem + AVH + eo * 2) = uh;
                *(uint2*)((char*)asmem + AVL + eo * 2) = ul;
            }
        }
        __syncthreads();

        // ---- S = Q K^T (3-pass split) ----
        float s[8][4];
#pragma unroll
        for (int i = 0; i < 8; i++)
#pragma unroll
            for (int j = 0; j < 4; j++) s[i][j] = 0.f;
#pragma unroll
        for (int ks = 0; ks < 4; ks++) {
#pragma unroll
            for (int np = 0; np < 4; np++) {
                uint32_t off = (uint32_t)(np * 16 + brow) * (APITCH * 2) + ks * 32 + bcolB;
                uint32_t kh4[4], kl4[4];
                ldm_x4(kh4, sb + AKH + off);
                ldm_x4(kl4, sb + AKL + off);
                mma16816(s[2*np],   qfh[ks], kh4 + 0);
                mma16816(s[2*np+1], qfh[ks], kh4 + 2);
                mma16816(s[2*np],   qfh[ks], kl4 + 0);
                mma16816(s[2*np+1], qfh[ks], kl4 + 2);
                mma16816(s[2*np],   qfl[ks], kh4 + 0);
                mma16816(s[2*np+1], qfl[ks], kh4 + 2);
            }
        }

        // ---- causal mask on diagonal tile ----
        if (kb == qb) {
            const int rr0 = wid * 16 + (lane >> 2);
            const int cc0 = (lane & 3) * 2;
#pragma unroll
            for (int nt = 0; nt < 8; nt++) {
#pragma unroll
                for (int jj = 0; jj < 2; jj++) {
                    int col = nt * 8 + cc0 + jj;
                    if (col > rr0)     s[nt][jj]     = -CUDART_INF_F;
                    if (col > rr0 + 8) s[nt][2 + jj] = -CUDART_INF_F;
                }
            }
        }

        // ---- online softmax ----
        float mx0 = -CUDART_INF_F, mx1 = -CUDART_INF_F;
#pragma unroll
        for (int nt = 0; nt < 8; nt++) {
            mx0 = fmaxf(mx0, fmaxf(s[nt][0], s[nt][1]));
            mx1 = fmaxf(mx1, fmaxf(s[nt][2], s[nt][3]));
        }
        mx0 = fmaxf(mx0, __shfl_xor_sync(0xffffffffu, mx0, 1));
        mx0 = fmaxf(mx0, __shfl_xor_sync(0xffffffffu, mx0, 2));
        mx1 = fmaxf(mx1, __shfl_xor_sync(0xffffffffu, mx1, 1));
        mx1 = fmaxf(mx1, __shfl_xor_sync(0xffffffffu, mx1, 2));
        const float mn0 = fmaxf(m0, mx0), mn1 = fmaxf(m1, mx1);
        const float cr0 = __expf(m0 - mn0), cr1 = __expf(m1 - mn1);
        float sum0 = 0.f, sum1 = 0.f;
        uint32_t pah[4][4], pal[4][4];
#pragma unroll
        for (int kt = 0; kt < 4; kt++) {
#pragma unroll
            for (int hh = 0; hh < 2; hh++) {
                const int nt = 2 * kt + hh;
                float p00 = __expf(s[nt][0] - mn0);
                float p01 = __expf(s[nt][1] - mn0);
                float p10 = __expf(s[nt][2] - mn1);
                float p11 = __expf(s[nt][3] - mn1);
                sum0 += p00 + p01;
                sum1 += p10 + p11;
                __nv_bfloat16 b00 = __float2bfloat16(p00), b01 = __float2bfloat16(p01);
                __nv_bfloat16 b10 = __float2bfloat16(p10), b11 = __float2bfloat16(p11);
                __nv_bfloat162 ph0 = __halves2bfloat162(b00, b01);
                __nv_bfloat162 ph1 = __halves2bfloat162(b10, b11);
                pah[kt][hh * 2 + 0] = *reinterpret_cast<uint32_t*>(&ph0);
                pah[kt][hh * 2 + 1] = *reinterpret_cast<uint32_t*>(&ph1);
                pal[kt][hh * 2 + 0] = packbf(p00 - __bfloat162float(b00),
                                             p01 - __bfloat162float(b01));
                pal[kt][hh * 2 + 1] = packbf(p10 - __bfloat162float(b10),
                                             p11 - __bfloat162float(b11));
            }
        }
        sum0 += __shfl_xor_sync(0xffffffffu, sum0, 1);
        sum0 += __shfl_xor_sync(0xffffffffu, sum0, 2);
        sum1 += __shfl_xor_sync(0xffffffffu, sum1, 1);
        sum1 += __shfl_xor_sync(0xffffffffu, sum1, 2);
        l0 = l0 * cr0 + sum0;  m0 = mn0;
        l1 = l1 * cr1 + sum1;  m1 = mn1;
#pragma unroll
        for (int nt = 0; nt < 8; nt++) {
            o[nt][0] *= cr0; o[nt][1] *= cr0;
            o[nt][2] *= cr1; o[nt][3] *= cr1;
        }

        // ---- O += P V (3-pass split), V via trans ldmatrix ----
#pragma unroll
        for (int kt = 0; kt < 4; kt++) {
#pragma unroll
            for (int p = 0; p < 4; p++) {
                uint32_t off = (uint32_t)(kt * 16 + vrow) * (APITCH * 2)
                             + (uint32_t)(p * 16 + vcol8) * 2;
                uint32_t fvh[4], fvl[4];
                ldm_x4_t(fvh, sb + AVH + off);
                ldm_x4_t(fvl, sb + AVL + off);
                mma16816(o[2*p],   pah[kt], fvh + 0);
                mma16816(o[2*p+1], pah[kt], fvh + 2);
                mma16816(o[2*p],   pah[kt], fvl + 0);
                mma16816(o[2*p+1], pah[kt], fvl + 2);
                mma16816(o[2*p],   pal[kt], fvh + 0);
                mma16816(o[2*p+1], pal[kt], fvh + 2);
            }
        }
    }

    // ---- epilogue: normalize, split, store z hi/lo ----
    const float inv0 = 1.f / l0, inv1 = 1.f / l1;
    const int gr0 = bb * SEQ + qb * 64 + wid * 16 + (lane >> 2);   // FIXED: batch offset
    const int gc  = h * HDIM + (lane & 3) * 2;
#pragma unroll
    for (int nt = 0; nt < 8; nt++) {
        float v0 = o[nt][0] * inv0, v1 = o[nt][1] * inv0;
        float v2 = o[nt][2] * inv1, v3 = o[nt][3] * inv1;
        __nv_bfloat16 h0 = __float2bfloat16(v0), h1 = __float2bfloat16(v1);
        __nv_bfloat16 h2 = __float2bfloat16(v2), h3 = __float2bfloat16(v3);
        __nv_bfloat162 ph0 = __halves2bfloat162(h0, h1);
        __nv_bfloat162 ph1 = __halves2bfloat162(h2, h3);
        uint32_t wl0 = packbf(v0 - __bfloat162float(h0), v1 - __bfloat162float(h1));
        uint32_t wl1 = packbf(v2 - __bfloat162float(h2), v3 - __bfloat162float(h3));
        size_t off0 = (size_t)gr0 * MODEL + gc + nt * 8;
        size_t off1 = (size_t)(gr0 + 8) * MODEL + gc + nt * 8;
        *(uint32_t*)(zh + off0) = *reinterpret_cast<uint32_t*>(&ph0);
        *(uint32_t*)(zl + off0) = wl0;
        *(uint32_t*)(zh + off1) = *reinterpret_cast<uint32_t*>(&ph1);
        *(uint32_t*)(zl + off1) = wl1;
    }
}

// ---------------------------------------------------------------------------
// Launch
// ---------------------------------------------------------------------------
extern "C" void kernel_launch(void* const* d_in, const int* in_sizes, int n_in,
                              void* d_out, int out_size)
{
    const float* x      = (const float*)d_in[0];
    const float* W_attn = (const float*)d_in[1];
    const float* b_attn = (const float*)d_in[2];
    const float* W_proj = (const float*)d_in[3];
    const float* b_proj = (const float*)d_in[4];
    float* out = (float*)d_out;

    float* qkv;             cudaGetSymbolAddress((void**)&qkv, g_qkv);
    __nv_bfloat16 *xh, *xl, *wah, *wal, *wph, *wpl, *zh, *zl;
    cudaGetSymbolAddress((void**)&xh,  g_xh);
    cudaGetSymbolAddress((void**)&xl,  g_xl);
    cudaGetSymbolAddress((void**)&wah, g_wah);
    cudaGetSymbolAddress((void**)&wal, g_wal);
    cudaGetSymbolAddress((void**)&wph, g_wph);
    cudaGetSymbolAddress((void**)&wpl, g_wpl);
    cudaGetSymbolAddress((void**)&zh,  g_zh);
    cudaGetSymbolAddress((void**)&zl,  g_zl);

    cudaFuncSetAttribute(gemm_mma, cudaFuncAttributeMaxDynamicSharedMemorySize, GSMEM);
    cudaFuncSetAttribute(attn_mma, cudaFuncAttributeMaxDynamicSharedMemorySize, ASMEMB);

    // Prep: split x; transpose+split weights
    split_convert<<<(ROWS * KDIM / 4 + 255) / 256, 256>>>(x, xh, xl, ROWS * KDIM / 4);
    transpose_split<<<dim3(QKVN / 32, KDIM / 32), dim3(32, 8)>>>(W_attn, wah, wal, KDIM, QKVN);
    transpose_split<<<dim3(MODEL / 32, KDIM / 32), dim3(32, 8)>>>(W_proj, wph, wpl, KDIM, MODEL);

    // QKV projection (tensor cores, 3-pass split bf16)
    gemm_mma<<<dim3(QKVN / 128, ROWS / 128), 256, GSMEM>>>(
        xh, xl, wah, wal, b_attn, qkv, QKVN);

    // causal attention -> z (bf16 hi/lo), tensor cores
    attn_mma<<<dim3(SEQ / 64, HEADS, BATCH), 128, ASMEMB>>>(qkv, zh, zl);

    // output projection (tensor cores)
    gemm_mma<<<dim3(MODEL / 128, ROWS / 128), 256, GSMEM>>>(
        zh, zl, wph, wpl, b_proj, out, MODEL);
}

// round 8
// speedup vs baseline: 2.4018x; 1.0823x over previous
#include <cuda_runtime.h>
#include <cuda_bf16.h>
#include <math_constants.h>
#include <cstdint>

// Problem constants
#define BATCH 2
#define SEQ   2048
#define MODEL 1024
#define HEADS 16
#define HDIM  64
#define ROWS  (BATCH*SEQ)          // 4096
#define QKVN  (3*MODEL)            // 3072
#define KDIM  1024

// ---------------------------------------------------------------------------
// Scratch (device globals: allocation-free)
// ---------------------------------------------------------------------------
__device__ __nv_bfloat16 g_qh[(size_t)ROWS * QKVN];   // qkv hi (q pre-scaled 1/8)
__device__ __nv_bfloat16 g_ql[(size_t)ROWS * QKVN];   // qkv lo
__device__ __nv_bfloat16 g_xh[(size_t)ROWS * KDIM];
__device__ __nv_bfloat16 g_xl[(size_t)ROWS * KDIM];
__device__ __nv_bfloat16 g_wah[(size_t)QKVN * KDIM];
__device__ __nv_bfloat16 g_wal[(size_t)QKVN * KDIM];
__device__ __nv_bfloat16 g_wph[(size_t)MODEL * KDIM];
__device__ __nv_bfloat16 g_wpl[(size_t)MODEL * KDIM];
__device__ __nv_bfloat16 g_zh[(size_t)ROWS * MODEL];
__device__ __nv_bfloat16 g_zl[(size_t)ROWS * MODEL];

// ---------------------------------------------------------------------------
// Helpers
// ---------------------------------------------------------------------------
__device__ __forceinline__ uint32_t smem_u32(const void* p) {
    uint32_t a;
    asm("{ .reg .u64 t; cvta.to.shared.u64 t, %1; cvt.u32.u64 %0, t; }"
        : "=r"(a) : "l"(p));
    return a;
}
__device__ __forceinline__ void ldm_x4(uint32_t* r, uint32_t a) {
    asm volatile("ldmatrix.sync.aligned.m8n8.x4.shared.b16 {%0,%1,%2,%3}, [%4];"
        : "=r"(r[0]), "=r"(r[1]), "=r"(r[2]), "=r"(r[3]) : "r"(a));
}
__device__ __forceinline__ void ldm_x4_t(uint32_t* r, uint32_t a) {
    asm volatile("ldmatrix.sync.aligned.m8n8.x4.trans.shared.b16 {%0,%1,%2,%3}, [%4];"
        : "=r"(r[0]), "=r"(r[1]), "=r"(r[2]), "=r"(r[3]) : "r"(a));
}
__device__ __forceinline__ void mma16816(float* c, const uint32_t* a, const uint32_t* b) {
    asm volatile("mma.sync.aligned.m16n8k16.row.col.f32.bf16.bf16.f32 "
        "{%0,%1,%2,%3}, {%4,%5,%6,%7}, {%8,%9}, {%0,%1,%2,%3};"
        : "+f"(c[0]), "+f"(c[1]), "+f"(c[2]), "+f"(c[3])
        : "r"(a[0]), "r"(a[1]), "r"(a[2]), "r"(a[3]), "r"(b[0]), "r"(b[1]));
}
__device__ __forceinline__ void cp16(uint32_t saddr, const void* gaddr) {
    asm volatile("cp.async.cg.shared.global [%0], [%1], 16;" :: "r"(saddr), "l"(gaddr));
}
__device__ __forceinline__ uint32_t packbf(float a, float b) {
    uint32_t r;
    asm("cvt.rn.satfinite.bf16x2.f32 %0, %1, %2;" : "=r"(r) : "f"(b), "f"(a));
    return r;
}
__device__ __forceinline__ void split4(float4 v, uint2& h, uint2& l) {
    __nv_bfloat16 h0 = __float2bfloat16(v.x), h1 = __float2bfloat16(v.y);
    __nv_bfloat16 h2 = __float2bfloat16(v.z), h3 = __float2bfloat16(v.w);
    __nv_bfloat16 l0 = __float2bfloat16(v.x - __bfloat162float(h0));
    __nv_bfloat16 l1 = __float2bfloat16(v.y - __bfloat162float(h1));
    __nv_bfloat16 l2 = __float2bfloat16(v.z - __bfloat162float(h2));
    __nv_bfloat16 l3 = __float2bfloat16(v.w - __bfloat162float(h3));
    __nv_bfloat162 ph0 = __halves2bfloat162(h0, h1), ph1 = __halves2bfloat162(h2, h3);
    __nv_bfloat162 pl0 = __halves2bfloat162(l0, l1), pl1 = __halves2bfloat162(l2, l3);
    h.x = *reinterpret_cast<uint32_t*>(&ph0); h.y = *reinterpret_cast<uint32_t*>(&ph1);
    l.x = *reinterpret_cast<uint32_t*>(&pl0); l.y = *reinterpret_cast<uint32_t*>(&pl1);
}

// ---------------------------------------------------------------------------
// Prep kernels
// ---------------------------------------------------------------------------
__global__ void split_convert(const float* __restrict__ x,
                              __nv_bfloat16* __restrict__ h,
                              __nv_bfloat16* __restrict__ l, int n4)
{
    int i = blockIdx.x * blockDim.x + threadIdx.x;
    if (i >= n4) return;
    float4 v = ((const float4*)x)[i];
    uint2 uh, ul;
    split4(v, uh, ul);
    ((uint2*)h)[i] = uh;
    ((uint2*)l)[i] = ul;
}

__global__ void transpose_split(const float* __restrict__ W,
                                __nv_bfloat16* __restrict__ Th,
                                __nv_bfloat16* __restrict__ Tl,
                                int Kd, int Nd)
{
    __shared__ float t[32][33];
    int n0 = blockIdx.x * 32, k0 = blockIdx.y * 32;
    int tx = threadIdx.x, ty = threadIdx.y;
#pragma unroll
    for (int j = 0; j < 32; j += 8)
        t[ty + j][tx] = W[(size_t)(k0 + ty + j) * Nd + n0 + tx];
    __syncthreads();
#pragma unroll
    for (int j = 0; j < 32; j += 8) {
        float v = t[tx][ty + j];
        int n = n0 + ty + j, k = k0 + tx;
        __nv_bfloat16 hb = __float2bfloat16(v);
        __nv_bfloat16 lb = __float2bfloat16(v - __bfloat162float(hb));
        Th[(size_t)n * Kd + k] = hb;
        Tl[(size_t)n * Kd + k] = lb;
    }
}

// ---------------------------------------------------------------------------
// mma.sync split-bf16 GEMM, single-stage smem, 2 CTAs/SM.
// MODE 0: C = fp32 (acc + bias)
// MODE 1: Ch/Cl = bf16 hi/lo of (acc + bias) * (col<MODEL ? 0.125 : 1)
// ---------------------------------------------------------------------------
#define GPITCH 144
#define GTILEB (128 * GPITCH)
#define GSTAGEB (4 * GTILEB)      // 73728 B, single stage

template<int MODE>
__global__ __launch_bounds__(256, 2) void gemm_mma(
    const __nv_bfloat16* __restrict__ Ah, const __nv_bfloat16* __restrict__ Al,
    const __nv_bfloat16* __restrict__ Bh, const __nv_bfloat16* __restrict__ Bl,
    const float* __restrict__ bias, float* __restrict__ C,
    __nv_bfloat16* __restrict__ Ch, __nv_bfloat16* __restrict__ Cl, int Nd)
{
    extern __shared__ char smem[];
    const uint32_t sbase = smem_u32(smem);
    const int tid  = threadIdx.x;
    const int wid  = tid >> 5, lane = tid & 31;
    const int bn   = blockIdx.x * 128;
    const int bm   = blockIdx.y * 128;
    const int wm0  = (wid & 3) * 32;
    const int wn0  = (wid >> 2) * 64;

    const int lrow = tid >> 3;
    const int lc   = tid & 7;

    const __nv_bfloat16* srcA_h = Ah + (size_t)bm * KDIM;
    const __nv_bfloat16* srcA_l = Al + (size_t)bm * KDIM;
    const __nv_bfloat16* srcB_h = Bh + (size_t)bn * KDIM;
    const __nv_bfloat16* srcB_l = Bl + (size_t)bn * KDIM;

    const int arow  = (lane & 7) + ((lane >> 3) & 1) * 8;
    const int acolB = ((lane >> 4) & 1) * 16;
    const int brow  = (lane & 7) + ((lane >> 4) & 1) * 8;
    const int bcolB = ((lane >> 3) & 1) * 16;

    float acc[16][4];
#pragma unroll
    for (int i = 0; i < 16; i++)
#pragma unroll
        for (int j = 0; j < 4; j++) acc[i][j] = 0.f;

    for (int c = 0; c < 16; c++) {
        // single-stage load (2 CTAs/SM cover the bubble)
        {
            const int k0 = c * 64;
            uint32_t so = sbase + lrow * GPITCH + lc * 16;
            const __nv_bfloat16* gA_h = srcA_h + (size_t)lrow * KDIM + k0 + lc * 8;
            const __nv_bfloat16* gA_l = srcA_l + (size_t)lrow * KDIM + k0 + lc * 8;
            const __nv_bfloat16* gB_h = srcB_h + (size_t)lrow * KDIM + k0 + lc * 8;
            const __nv_bfloat16* gB_l = srcB_l + (size_t)lrow * KDIM + k0 + lc * 8;
#pragma unroll
            for (int i = 0; i < 4; i++) {
                uint32_t sa = so + i * 32 * GPITCH;
                size_t   go = (size_t)i * 32 * KDIM;
                cp16(sa,               gA_h + go);
                cp16(sa + GTILEB,      gA_l + go);
                cp16(sa + 2 * GTILEB,  gB_h + go);
                cp16(sa + 3 * GTILEB,  gB_l + go);
            }
            asm volatile("cp.async.commit_group;" ::: "memory");
            asm volatile("cp.async.wait_group 0;" ::: "memory");
        }
        __syncthreads();

        const uint32_t ab  = sbase;
        const uint32_t alb = ab + GTILEB;
        const uint32_t bb  = ab + 2 * GTILEB;
        const uint32_t blb = ab + 3 * GTILEB;

#pragma unroll
        for (int ks = 0; ks < 4; ks++) {
            uint32_t fah[2][4], fal[2][4], fbh[4][4], fbl[4][4];
#pragma unroll
            for (int ma = 0; ma < 2; ma++) {
                uint32_t off = (uint32_t)(wm0 + ma * 16 + arow) * GPITCH + ks * 32 + acolB;
                ldm_x4(fah[ma], ab + off);
                ldm_x4(fal[ma], alb + off);
            }
#pragma unroll
            for (int na = 0; na < 4; na++) {
                uint32_t off = (uint32_t)(wn0 + na * 16 + brow) * GPITCH + ks * 32 + bcolB;
                ldm_x4(fbh[na], bb + off);
                ldm_x4(fbl[na], blb + off);
            }
#pragma unroll
            for (int ma = 0; ma < 2; ma++) {
#pragma unroll
                for (int na = 0; na < 4; na++) {
                    float* c0 = acc[ma * 8 + na * 2];
                    float* c1 = acc[ma * 8 + na * 2 + 1];
                    mma16816(c0, fah[ma], fbh[na]);
                    mma16816(c1, fah[ma], fbh[na] + 2);
                    mma16816(c0, fah[ma], fbl[na]);
                    mma16816(c1, fah[ma], fbl[na] + 2);
                    mma16816(c0, fal[ma], fbh[na]);
                    mma16816(c1, fal[ma], fbh[na] + 2);
                }
            }
        }
        __syncthreads();
    }

    const int er = bm + wm0 + (lane >> 2);
    const int ec = bn + wn0 + (lane & 3) * 2;
#pragma unroll
    for (int ma = 0; ma < 2; ma++) {
#pragma unroll
        for (int na = 0; na < 8; na++) {
            const float* a4 = acc[ma * 8 + na];
            int row = er + ma * 16;
            int col = ec + na * 8;
            float b0 = __ldg(bias + col), b1 = __ldg(bias + col + 1);
            if (MODE == 0) {
                float2 v0 = make_float2(a4[0] + b0, a4[1] + b1);
                float2 v1 = make_float2(a4[2] + b0, a4[3] + b1);
                *(float2*)(C + (size_t)row * Nd + col)       = v0;
                *(float2*)(C + (size_t)(row + 8) * Nd + col) = v1;
            } else {
                float sc = (col < MODEL) ? 0.125f : 1.f;
                float v0 = (a4[0] + b0) * sc, v1 = (a4[1] + b1) * sc;
                float v2 = (a4[2] + b0) * sc, v3 = (a4[3] + b1) * sc;
                __nv_bfloat16 h0 = __float2bfloat16(v0), h1 = __float2bfloat16(v1);
                __nv_bfloat16 h2 = __float2bfloat16(v2), h3 = __float2bfloat16(v3);
                __nv_bfloat162 p0 = __halves2bfloat162(h0, h1);
                __nv_bfloat162 p1 = __halves2bfloat162(h2, h3);
                uint32_t wl0 = packbf(v0 - __bfloat162float(h0), v1 - __bfloat162float(h1));
                uint32_t wl1 = packbf(v2 - __bfloat162float(h2), v3 - __bfloat162float(h3));
                size_t o0 = (size_t)row * Nd + col, o1 = (size_t)(row + 8) * Nd + col;
                *(uint32_t*)(Ch + o0) = *reinterpret_cast<uint32_t*>(&p0);
                *(uint32_t*)(Cl + o0) = wl0;
                *(uint32_t*)(Ch + o1) = *reinterpret_cast<uint32_t*>(&p1);
                *(uint32_t*)(Cl + o1) = wl1;
            }
        }
    }
}

// ---------------------------------------------------------------------------
// Tensor-core causal flash attention; consumes pre-split bf16 qkv (q scaled).
// CTA: 64 q-rows x (head, batch); 4 warps; KV double-buffered via cp.async.
// ---------------------------------------------------------------------------
#define APITCH 72                              // bf16/row (144 B)
#define ATILE  9216                            // 64*144
#define AQH 0
#define AQL ATILE
#define AKV0 (2 * ATILE)                       // stage base; KH,KL,VH,VL
#define AKVSTAGE (4 * ATILE)                   // 36864
#define ASMEMB (2 * ATILE + 2 * AKVSTAGE)      // 92160

__global__ __launch_bounds__(128) void attn_mma(
    const __nv_bfloat16* __restrict__ qh, const __nv_bfloat16* __restrict__ ql,
    __nv_bfloat16* __restrict__ zh, __nv_bfloat16* __restrict__ zl)
{
    extern __shared__ __nv_bfloat16 asmem[];
    const uint32_t sb = smem_u32(asmem);
    const int tid = threadIdx.x, lane = tid & 31, wid = tid >> 5;
    const int qb = blockIdx.x, h = blockIdx.y, bb = blockIdx.z;

    const size_t rowbase = (size_t)(bb * SEQ) * QKVN;
    const int hc = h * HDIM;

    // loader mapping: 512 chunks per 64x64 tile; 4 per thread
    const int lr = tid >> 1;                 // 0..63 rows (2 threads/row)
    const int lc4 = (tid & 1) * 4;           // chunk 0..3 or 4..7

    auto load_q = [&] {
#pragma unroll
        for (int j = 0; j < 4; j++) {
            size_t g = rowbase + (size_t)(qb * 64 + lr) * QKVN + hc + (lc4 + j) * 8;
            uint32_t d = (uint32_t)(lr * 144 + (lc4 + j) * 16);
            cp16(sb + AQH + d, qh + g);
            cp16(sb + AQL + d, ql + g);
        }
    };
    auto load_kv = [&](int stage, int kb) {
        uint32_t sbb = sb + AKV0 + stage * AKVSTAGE;
#pragma unroll
        for (int j = 0; j < 4; j++) {
            size_t gk = rowbase + (size_t)(kb * 64 + lr) * QKVN + MODEL + hc + (lc4 + j) * 8;
            size_t gv = gk + MODEL;
            uint32_t d = (uint32_t)(lr * 144 + (lc4 + j) * 16);
            cp16(sbb + d,             qh + gk);
            cp16(sbb + ATILE + d,     ql + gk);
            cp16(sbb + 2 * ATILE + d, qh + gv);
            cp16(sbb + 3 * ATILE + d, ql + gv);
        }
    };

    load_q();
    load_kv(0, 0);
    asm volatile("cp.async.commit_group;" ::: "memory");

    const int arow  = (lane & 7) + ((lane >> 3) & 1) * 8;
    const int acolB = ((lane >> 4) & 1) * 16;
    const int brow  = (lane & 7) + ((lane >> 4) & 1) * 8;
    const int bcolB = ((lane >> 3) & 1) * 16;
    const int vrow  = (lane & 7) + ((lane >> 3) & 1) * 8;
    const int vcol8 = ((lane >> 4) & 1) * 8;

    uint32_t qfh[4][4], qfl[4][4];
    float m0 = -CUDART_INF_F, m1 = -CUDART_INF_F, l0 = 0.f, l1 = 0.f;
    float o[8][4];
#pragma unroll
    for (int i = 0; i < 8; i++)
#pragma unroll
        for (int j = 0; j < 4; j++) o[i][j] = 0.f;

    for (int kb = 0; kb <= qb; kb++) {
        if (kb + 1 <= qb) {
            load_kv((kb + 1) & 1, kb + 1);
            asm volatile("cp.async.commit_group;" ::: "memory");
            asm volatile("cp.async.wait_group 1;" ::: "memory");
        } else {
            asm volatile("cp.async.wait_group 0;" ::: "memory");
        }
        __syncthreads();

        if (kb == 0) {
#pragma unroll
            for (int ks = 0; ks < 4; ks++) {
                uint32_t off = (uint32_t)(wid * 16 + arow) * (APITCH * 2) + ks * 32 + acolB;
                ldm_x4(qfh[ks], sb + AQH + off);
                ldm_x4(qfl[ks], sb + AQL + off);
            }
        }

        const uint32_t kvb = sb + AKV0 + (kb & 1) * AKVSTAGE;
        const uint32_t kh_b = kvb, kl_b = kvb + ATILE;
        const uint32_t vh_b = kvb + 2 * ATILE, vl_b = kvb + 3 * ATILE;

        // ---- S = Q K^T (3-pass split) ----
        float s[8][4];
#pragma unroll
        for (int i = 0; i < 8; i++)
#pragma unroll
            for (int j = 0; j < 4; j++) s[i][j] = 0.f;
#pragma unroll
        for (int ks = 0; ks < 4; ks++) {
#pragma unroll
            for (int np = 0; np < 4; np++) {
                uint32_t off = (uint32_t)(np * 16 + brow) * (APITCH * 2) + ks * 32 + bcolB;
                uint32_t kh4[4], kl4[4];
                ldm_x4(kh4, kh_b + off);
                ldm_x4(kl4, kl_b + off);
                mma16816(s[2*np],   qfh[ks], kh4 + 0);
                mma16816(s[2*np+1], qfh[ks], kh4 + 2);
                mma16816(s[2*np],   qfh[ks], kl4 + 0);
                mma16816(s[2*np+1], qfh[ks], kl4 + 2);
                mma16816(s[2*np],   qfl[ks], kh4 + 0);
                mma16816(s[2*np+1], qfl[ks], kh4 + 2);
            }
        }

        if (kb == qb) {
            const int rr0 = wid * 16 + (lane >> 2);
            const int cc0 = (lane & 3) * 2;
#pragma unroll
            for (int nt = 0; nt < 8; nt++) {
#pragma unroll
                for (int jj = 0; jj < 2; jj++) {
                    int col = nt * 8 + cc0 + jj;
                    if (col > rr0)     s[nt][jj]     = -CUDART_INF_F;
                    if (col > rr0 + 8) s[nt][2 + jj] = -CUDART_INF_F;
                }
            }
        }

        // ---- online softmax ----
        float mx0 = -CUDART_INF_F, mx1 = -CUDART_INF_F;
#pragma unroll
        for (int nt = 0; nt < 8; nt++) {
            mx0 = fmaxf(mx0, fmaxf(s[nt][0], s[nt][1]));
            mx1 = fmaxf(mx1, fmaxf(s[nt][2], s[nt][3]));
        }
        mx0 = fmaxf(mx0, __shfl_xor_sync(0xffffffffu, mx0, 1));
        mx0 = fmaxf(mx0, __shfl_xor_sync(0xffffffffu, mx0, 2));
        mx1 = fmaxf(mx1, __shfl_xor_sync(0xffffffffu, mx1, 1));
        mx1 = fmaxf(mx1, __shfl_xor_sync(0xffffffffu, mx1, 2));
        const float mn0 = fmaxf(m0, mx0), mn1 = fmaxf(m1, mx1);
        const float cr0 = __expf(m0 - mn0), cr1 = __expf(m1 - mn1);
        float sum0 = 0.f, sum1 = 0.f;
        uint32_t pah[4][4], pal[4][4];
#pragma unroll
        for (int kt = 0; kt < 4; kt++) {
#pragma unroll
            for (int hh = 0; hh < 2; hh++) {
                const int nt = 2 * kt + hh;
                float p00 = __expf(s[nt][0] - mn0);
                float p01 = __expf(s[nt][1] - mn0);
                float p10 = __expf(s[nt][2] - mn1);
                float p11 = __expf(s[nt][3] - mn1);
                sum0 += p00 + p01;
                sum1 += p10 + p11;
                __nv_bfloat16 b00 = __float2bfloat16(p00), b01 = __float2bfloat16(p01);
                __nv_bfloat16 b10 = __float2bfloat16(p10), b11 = __float2bfloat16(p11);
                __nv_bfloat162 ph0 = __halves2bfloat162(b00, b01);
                __nv_bfloat162 ph1 = __halves2bfloat162(b10, b11);
                pah[kt][hh * 2 + 0] = *reinterpret_cast<uint32_t*>(&ph0);
                pah[kt][hh * 2 + 1] = *reinterpret_cast<uint32_t*>(&ph1);
                pal[kt][hh * 2 + 0] = packbf(p00 - __bfloat162float(b00),
                                             p01 - __bfloat162float(b01));
                pal[kt][hh * 2 + 1] = packbf(p10 - __bfloat162float(b10),
                                             p11 - __bfloat162float(b11));
            }
        }
        sum0 += __shfl_xor_sync(0xffffffffu, sum0, 1);
        sum0 += __shfl_xor_sync(0xffffffffu, sum0, 2);
        sum1 += __shfl_xor_sync(0xffffffffu, sum1, 1);
        sum1 += __shfl_xor_sync(0xffffffffu, sum1, 2);
        l0 = l0 * cr0 + sum0;  m0 = mn0;
        l1 = l1 * cr1 + sum1;  m1 = mn1;
#pragma unroll
        for (int nt = 0; nt < 8; nt++) {
            o[nt][0] *= cr0; o[nt][1] *= cr0;
            o[nt][2] *= cr1; o[nt][3] *= cr1;
        }

        // ---- O += P V (3-pass split), V via trans ldmatrix ----
#pragma unroll
        for (int kt = 0; kt < 4; kt++) {
#pragma unroll
            for (int p = 0; p < 4; p++) {
                uint32_t off = (uint32_t)(kt * 16 + vrow) * (APITCH * 2)
                             + (uint32_t)(p * 16 + vcol8) * 2;
                uint32_t fvh[4], fvl[4];
                ldm_x4_t(fvh, vh_b + off);
                ldm_x4_t(fvl, vl_b + off);
                mma16816(o[2*p],   pah[kt], fvh + 0);
                mma16816(o[2*p+1], pah[kt], fvh + 2);
                mma16816(o[2*p],   pah[kt], fvl + 0);
                mma16816(o[2*p+1], pah[kt], fvl + 2);
                mma16816(o[2*p],   pal[kt], fvh + 0);
                mma16816(o[2*p+1], pal[kt], fvh + 2);
            }
        }
        __syncthreads();
    }

    // ---- epilogue: normalize, split, store z hi/lo ----
    const float inv0 = 1.f / l0, inv1 = 1.f / l1;
    const int gr0 = bb * SEQ + qb * 64 + wid * 16 + (lane >> 2);
    const int gc  = h * HDIM + (lane & 3) * 2;
#pragma unroll
    for (int nt = 0; nt < 8; nt++) {
        float v0 = o[nt][0] * inv0, v1 = o[nt][1] * inv0;
        float v2 = o[nt][2] * inv1, v3 = o[nt][3] * inv1;
        __nv_bfloat16 h0 = __float2bfloat16(v0), h1 = __float2bfloat16(v1);
        __nv_bfloat16 h2 = __float2bfloat16(v2), h3 = __float2bfloat16(v3);
        __nv_bfloat162 ph0 = __halves2bfloat162(h0, h1);
        __nv_bfloat162 ph1 = __halves2bfloat162(h2, h3);
        uint32_t wl0 = packbf(v0 - __bfloat162float(h0), v1 - __bfloat162float(h1));
        uint32_t wl1 = packbf(v2 - __bfloat162float(h2), v3 - __bfloat162float(h3));
        size_t off0 = (size_t)gr0 * MODEL + gc + nt * 8;
        size_t off1 = (size_t)(gr0 + 8) * MODEL + gc + nt * 8;
        *(uint32_t*)(zh + off0) = *reinterpret_cast<uint32_t*>(&ph0);
        *(uint32_t*)(zl + off0) = wl0;
        *(uint32_t*)(zh + off1) = *reinterpret_cast<uint32_t*>(&ph1);
        *(uint32_t*)(zl + off1) = wl1;
    }
}

// ---------------------------------------------------------------------------
// Launch
// ---------------------------------------------------------------------------
extern "C" void kernel_launch(void* const* d_in, const int* in_sizes, int n_in,
                              void* d_out, int out_size)
{
    const float* x      = (const float*)d_in[0];
    const float* W_attn = (const float*)d_in[1];
    const float* b_attn = (const float*)d_in[2];
    const float* W_proj = (const float*)d_in[3];
    const float* b_proj = (const float*)d_in[4];
    float* out = (float*)d_out;

    __nv_bfloat16 *qh, *ql, *xh, *xl, *wah, *wal, *wph, *wpl, *zh, *zl;
    cudaGetSymbolAddress((void**)&qh,  g_qh);
    cudaGetSymbolAddress((void**)&ql,  g_ql);
    cudaGetSymbolAddress((void**)&xh,  g_xh);
    cudaGetSymbolAddress((void**)&xl,  g_xl);
    cudaGetSymbolAddress((void**)&wah, g_wah);
    cudaGetSymbolAddress((void**)&wal, g_wal);
    cudaGetSymbolAddress((void**)&wph, g_wph);
    cudaGetSymbolAddress((void**)&wpl, g_wpl);
    cudaGetSymbolAddress((void**)&zh,  g_zh);
    cudaGetSymbolAddress((void**)&zl,  g_zl);

    cudaFuncSetAttribute(gemm_mma<0>, cudaFuncAttributeMaxDynamicSharedMemorySize, GSTAGEB);
    cudaFuncSetAttribute(gemm_mma<1>, cudaFuncAttributeMaxDynamicSharedMemorySize, GSTAGEB);
    cudaFuncSetAttribute(attn_mma, cudaFuncAttributeMaxDynamicSharedMemorySize, ASMEMB);

    // Prep: split x; transpose+split weights
    split_convert<<<(ROWS * KDIM / 4 + 255) / 256, 256>>>(x, xh, xl, ROWS * KDIM / 4);
    transpose_split<<<dim3(QKVN / 32, KDIM / 32), dim3(32, 8)>>>(W_attn, wah, wal, KDIM, QKVN);
    transpose_split<<<dim3(MODEL / 32, KDIM / 32), dim3(32, 8)>>>(W_proj, wph, wpl, KDIM, MODEL);

    // QKV projection -> split bf16 qkv (q pre-scaled by 1/8)
    gemm_mma<1><<<dim3(QKVN / 128, ROWS / 128), 256, GSTAGEB>>>(
        xh, xl, wah, wal, b_attn, nullptr, qh, ql, QKVN);

    // causal attention -> z (bf16 hi/lo)
    attn_mma<<<dim3(SEQ / 64, HEADS, BATCH), 128, ASMEMB>>>(qh, ql, zh, zl);

    // output projection -> fp32 out
    gemm_mma<0><<<dim3(MODEL / 128, ROWS / 128), 256, GSTAGEB>>>(
        zh, zl, wph, wpl, b_proj, out, nullptr, nullptr, MODEL);
}